// round 16
// baseline (speedup 1.0000x reference)
#include <cuda_runtime.h>
#include <math.h>

#define BB 16
#define TT 96
#define NN 256
#define CC 9
#define MM (NN*CC)          // 2304
#define EE 128
#define HID 64
#define KNN 8
#define PRED 96
#define BM (BB*MM)          // 36864
#define BN (BB*NN)          // 4096
#define NSL 6               // knn candidate slices (grid 9*16*6=864 = one wave)
#define SLW (MM/NSL)        // 384 candidates per slice
#define NZB ((BM + 255)/256)      // indeg zero blocks (144)
#define NTB (BN/256)              // trend blocks (16)

// ---------------- device scratch (static, no allocation) ----------------
__device__ float  d_trend[BN*TT];          // (b,n,t)
__device__ float2 d_sg[BM];                // spectral node scalars
__device__ int    d_idx[BM*KNN];
__device__ float  d_indeg[BM];
__device__ float  d_pd[BM*NSL*KNN];        // partial knn distances
__device__ int    d_pi[BM*NSL*KNN];        // partial knn indices
__device__ float2 d_g[BM*CC];              // (r,i) per (node, freq)
__device__ float2 d_g2[BM*CC];
__device__ float  d_H[BN*TT];
__device__ float  d_Ar[CC*EE], d_Ai[CC*EE];
__device__ float  d_tw96c[96], d_tw96s[96];

__device__ __forceinline__ void red_add_f32x2(float2* addr, float a, float b) {
    asm volatile("red.global.add.v2.f32 [%0], {%1, %2};" :: "l"(addr), "f"(a), "f"(b) : "memory");
}

// ---------------- merged: zero indeg + proj-weight precompute + tw96 + trend/DFT ----------------
__global__ void k_init(const float* __restrict__ x,
                       const float* __restrict__ femb,
                       const float* __restrict__ frWr,
                       const float* __restrict__ frWi) {
    int bid = blockIdx.x;
    if (bid < NZB) {
        int i = bid * 256 + threadIdx.x;
        if (i < BM) d_indeg[i] = 0.f;
        return;
    }
    if (bid < NZB + CC + 1) {
        int pb = bid - NZB;                     // 0..CC
        if (threadIdx.x >= 128) return;
        if (pb < CC) {
            int c = pb, e = threadIdx.x;
            float sr = 0.f, si = 0.f;
            const float* fe = femb + c*EE;
            const float* wr = frWr + e*EE;
            const float* wi = frWi + e*EE;
            #pragma unroll 8
            for (int k = 0; k < EE; ++k) {
                float f = fe[k];
                sr += f * wr[k];
                si += f * wi[k];
            }
            d_Ar[c*EE + e] = sr;
            d_Ai[c*EE + e] = si;
        } else {
            int t = threadIdx.x;
            if (t < 96) {
                double a = 2.0 * 3.14159265358979323846 * (double)t / 96.0;
                d_tw96c[t] = (float)cos(a);
                d_tw96s[t] = (float)sin(a);
            }
        }
        return;
    }
    // ---- trend (moving avg) + truncated 16-pt rDFT ----
    int id = (bid - (NZB + CC + 1)) * 256 + threadIdx.x;
    if (id >= BN) return;
    int b = id >> 8, n = id & 255;
    const float* xb = x + (size_t)b*TT*NN + n;
    float twc[16], tws[16];
    #pragma unroll
    for (int t = 0; t < 16; ++t) sincospif(t * 0.125f, &tws[t], &twc[t]);
    float s[16];
    float xprev = xb[0];
    float xc = xb[0];
    for (int t = 0; t < TT; ++t) {
        float xn = (t < TT-1) ? xb[(t+1)*NN] : xc;
        float tr = (xprev + xc + xn) / 3.0f;
        d_trend[(size_t)id*TT + t] = tr;
        if (t < 16) s[t] = xc - tr;
        xprev = xc; xc = xn;
    }
    int base = b*MM + n*CC;
    #pragma unroll
    for (int c = 0; c < CC; ++c) {
        float sr = 0.f, si = 0.f;
        #pragma unroll
        for (int t = 0; t < 16; ++t) {
            int a = (c*t) & 15;
            sr += s[t] * twc[a];
            si -= s[t] * tws[a];
        }
        d_sg[base + c] = make_float2(0.25f * sr, 0.25f * si);
    }
}

// sorted-insert of v into ascending bd[0..7] (distances only): 16 FMNMX, no SELs
#define INS8(v) do { \
    float m0 = fminf(bd[0], (v)); \
    float m1 = fminf(bd[1], (v)); \
    float m2 = fminf(bd[2], (v)); \
    float m3 = fminf(bd[3], (v)); \
    float m4 = fminf(bd[4], (v)); \
    float m5 = fminf(bd[5], (v)); \
    float m6 = fminf(bd[6], (v)); \
    float m7 = fminf(bd[7], (v)); \
    bd[7] = fmaxf(bd[6], m7); \
    bd[6] = fmaxf(bd[5], m6); \
    bd[5] = fmaxf(bd[4], m5); \
    bd[4] = fmaxf(bd[3], m4); \
    bd[3] = fmaxf(bd[2], m3); \
    bd[2] = fmaxf(bd[1], m2); \
    bd[1] = fmaxf(bd[0], m1); \
    bd[0] = m0; \
} while (0)

// composite (d2, j) bubble insert into md/mi8[0..7]
#define INSC(vd_, vi_) do { \
    float vd = (vd_); int vi = (vi_); \
    _Pragma("unroll") \
    for (int k = 0; k < KNN; ++k) { \
        bool lt = (vd < md[k]) || (vd == md[k] && vi < mi8[k]); \
        float od = md[k]; int oi = mi8[k]; \
        md[k]  = lt ? vd : od; \
        mi8[k] = lt ? vi : oi; \
        vd = lt ? od : vd; \
        vi = lt ? oi : vi; \
    } \
} while (0)

// ---------------- KNN partial: two-pass (threshold, then exact top-8 via INSC) ----------------
// d2' = |c|^2 - 2<me, c>  (self-sq dropped: constant per node -> same ordering, merge-safe)
// grid (MM/256, BB, NSL), block 256 — 864 blocks = single wave
__global__ void __launch_bounds__(256) k_knn_part() {
    __shared__ float4 sf[MM];   // (x, y, sq, 0) 36.9KB
    int b = blockIdx.y;
    int z = blockIdx.z;
    for (int m = threadIdx.x; m < MM; m += 256) {
        float2 v = d_sg[b*MM + m];
        sf[m] = make_float4(v.x, v.y, v.x*v.x + v.y*v.y, 0.f);
    }
    __syncthreads();
    int i = blockIdx.x * 256 + threadIdx.x;   // node 0..MM-1
    float4 me = sf[i];
    float n2x = -2.0f * me.x, n2y = -2.0f * me.y;
    const float FINF = __int_as_float(0x7f800000);
    int j0 = z * SLW, j1 = j0 + SLW;
    int e1 = min(j1, i);       // [j0, e1) excludes self
    int s2 = max(j0, i + 1);   // [s2, j1) excludes self
    // ---- pass 1: find the 8 smallest distances (values only) ----
    float bd[KNN];
    #pragma unroll
    for (int k = 0; k < KNN; ++k) bd[k] = FINF;
    #pragma unroll 4
    for (int j = j0; j < e1; ++j) {
        float4 c = sf[j];
        float d2 = fmaf(n2y, c.y, fmaf(n2x, c.x, c.z));
        INS8(d2);
    }
    #pragma unroll 4
    for (int j = s2; j < j1; ++j) {
        float4 c = sf[j];
        float d2 = fmaf(n2y, c.y, fmaf(n2x, c.x, c.z));
        INS8(d2);
    }
    float thr = bd[7];
    // ---- pass 2: exact top-8 by (d2, j) among candidates <= thr (no local memory) ----
    float md[KNN]; int mi8[KNN];
    #pragma unroll
    for (int k = 0; k < KNN; ++k) { md[k] = FINF; mi8[k] = 0x7fffffff; }
    #pragma unroll 4
    for (int j = j0; j < e1; ++j) {
        float4 c = sf[j];
        float d2 = fmaf(n2y, c.y, fmaf(n2x, c.x, c.z));
        if (d2 <= thr) INSC(d2, j);
    }
    #pragma unroll 4
    for (int j = s2; j < j1; ++j) {
        float4 c = sf[j];
        float d2 = fmaf(n2y, c.y, fmaf(n2x, c.x, c.z));
        if (d2 <= thr) INSC(d2, j);
    }
    int base = ((b*MM + i)*NSL + z) * KNN;
    #pragma unroll
    for (int k = 0; k < KNN; ++k) { d_pd[base + k] = md[k]; d_pi[base + k] = mi8[k]; }
}

// ---------------- KNN merge: 2 threads/node, float4 loads, snapshot-then-merge ----------------
__global__ void __launch_bounds__(256) k_knn_merge() {
    int gtid = blockIdx.x * 256 + threadIdx.x;
    int m = gtid >> 1;          // node
    int half = gtid & 1;        // 0: slices 0-2, 1: slices 3-5
    if (m >= BM) return;
    int b = m / MM;
    const float FINF = __int_as_float(0x7f800000);
    float md[KNN]; int mi8[KNN];
    #pragma unroll
    for (int k = 0; k < KNN; ++k) { md[k] = FINF; mi8[k] = 0x7fffffff; }
    const float4* pd4 = (const float4*)&d_pd[m*(NSL*KNN) + half*24];
    const int4*  pi4 = (const int4*) &d_pi[m*(NSL*KNN) + half*24];
    #pragma unroll
    for (int v = 0; v < 6; ++v) {
        float4 dv = pd4[v];
        int4  jv = pi4[v];
        INSC(dv.x, jv.x);
        INSC(dv.y, jv.y);
        INSC(dv.z, jv.z);
        INSC(dv.w, jv.w);
    }
    // snapshot partner's PRE-merge list first (avoids register race), then merge
    float pdl[KNN]; int pjl[KNN];
    #pragma unroll
    for (int k = 0; k < KNN; ++k) {
        pdl[k] = __shfl_xor_sync(0xffffffffu, md[k], 1);
        pjl[k] = __shfl_xor_sync(0xffffffffu, mi8[k], 1);
    }
    #pragma unroll
    for (int k = 0; k < KNN; ++k) INSC(pdl[k], pjl[k]);
    if (half == 0) {
        #pragma unroll
        for (int k = 0; k < KNN; ++k) {
            d_idx[m*KNN + k] = mi8[k];
            atomicAdd(&d_indeg[b*MM + mi8[k]], 1.0f);
        }
    }
}

// ---------------- g forward gather: 2 threads/node (4 nb each), writes d_g ----------------
__global__ void k_gf() {
    int gtid = blockIdx.x * blockDim.x + threadIdx.x;
    int i = gtid >> 1;
    int half = gtid & 1;
    if (i >= BM) return;
    int b = i / MM;
    float di = d_indeg[i] + 8.0f + 1e-8f;
    float gr[CC], gi[CC];
    #pragma unroll
    for (int c = 0; c < CC; ++c) { gr[c] = 0.f; gi[c] = 0.f; }
    int4 nb = *(const int4*)&d_idx[i*KNN + half*4];
    int js[4] = {nb.x, nb.y, nb.z, nb.w};
    #pragma unroll
    for (int k = 0; k < 4; ++k) {
        int j = b*MM + js[k];
        float w = 0.5f * rsqrtf(di * (d_indeg[j] + 8.0f + 1e-8f));
        float2 s = d_sg[j];
        int cj = j % CC;
        float wx = w*s.x, wy = w*s.y;
        #pragma unroll
        for (int c = 0; c < CC; ++c) if (c == cj) { gr[c] += wx; gi[c] += wy; }
    }
    #pragma unroll
    for (int c = 0; c < CC; ++c) {
        gr[c] += __shfl_xor_sync(0xffffffffu, gr[c], 1);
        gi[c] += __shfl_xor_sync(0xffffffffu, gi[c], 1);
    }
    if (half == 0) {
        #pragma unroll
        for (int c = 0; c < CC; ++c) d_g[i*CC + c] = make_float2(gr[c], gi[c]);
    }
}

// ---------------- g reverse scatter: 1 red.v2 per edge ----------------
__global__ void k_gr() {
    int e = blockIdx.x * blockDim.x + threadIdx.x;
    if (e >= BM*KNN) return;
    int mi = e >> 3;
    int b = mi / MM;
    int mj = b*MM + d_idx[e];
    float w = 0.5f * rsqrtf((d_indeg[mi]+8.0f+1e-8f) * (d_indeg[mj]+8.0f+1e-8f));
    int ci = mi % CC;
    float2 si = d_sg[mi];
    red_add_f32x2(&d_g[mj*CC + ci], w*si.x, w*si.y);
}

// ---------------- g2 forward gather: 2 threads/node (4 nb each), writes d_g2 ----------------
__global__ void k_g2f() {
    int gtid = blockIdx.x * blockDim.x + threadIdx.x;
    int i = gtid >> 1;
    int half = gtid & 1;
    if (i >= BM) return;
    int b = i / MM;
    float di = d_indeg[i] + 8.0f + 1e-8f;
    float ar[CC], ai[CC];
    #pragma unroll
    for (int c = 0; c < CC; ++c) { ar[c] = 0.f; ai[c] = 0.f; }
    int4 nb = *(const int4*)&d_idx[i*KNN + half*4];
    int js[4] = {nb.x, nb.y, nb.z, nb.w};
    #pragma unroll
    for (int k = 0; k < 4; ++k) {
        int j = b*MM + js[k];
        float w = 0.5f * rsqrtf(di * (d_indeg[j] + 8.0f + 1e-8f));
        #pragma unroll
        for (int c = 0; c < CC; ++c) {
            float2 gj = d_g[j*CC + c];
            ar[c] += w * gj.x;
            ai[c] += w * gj.y;
        }
    }
    #pragma unroll
    for (int c = 0; c < CC; ++c) {
        ar[c] += __shfl_xor_sync(0xffffffffu, ar[c], 1);
        ai[c] += __shfl_xor_sync(0xffffffffu, ai[c], 1);
    }
    if (half == 0) {
        #pragma unroll
        for (int c = 0; c < CC; ++c) d_g2[i*CC + c] = make_float2(ar[c], ai[c]);
    }
}

// ---------------- g2 reverse scatter: 9 red.v2 per edge ----------------
__global__ void k_g2r() {
    int e = blockIdx.x * blockDim.x + threadIdx.x;
    if (e >= BM*KNN) return;
    int mi = e >> 3;
    int b = mi / MM;
    int mj = b*MM + d_idx[e];
    float w = 0.5f * rsqrtf((d_indeg[mi]+8.0f+1e-8f) * (d_indeg[mj]+8.0f+1e-8f));
    #pragma unroll
    for (int c = 0; c < CC; ++c) {
        float2 gi = d_g[mi*CC + c];
        red_add_f32x2(&d_g2[mj*CC + c], w*gi.x, w*gi.y);
    }
}

// fast silu: MUFU-based exp + divide (rel err ~1e-6, tol is 1e-3)
__device__ __forceinline__ float siluf(float v) {
    return __fdividef(v, 1.0f + __expf(-v));
}

// ---------------- fused: proj (9 nodes) + irfft(96) + inorm + silu, warp per (b,n) row ----------------
__global__ void __launch_bounds__(256) k_proj_irfft(const float* __restrict__ approx,
                                                    const float* __restrict__ theta,
                                                    const float* __restrict__ eoWr,
                                                    const float* __restrict__ eoWi,
                                                    const float* __restrict__ n1w,
                                                    const float* __restrict__ n1b) {
    int gtid = blockIdx.x * blockDim.x + threadIdx.x;
    int row = gtid >> 5;
    int lane = gtid & 31;
    if (row >= BN) return;
    int b = row >> 8, n = row & 255;
    int mbase = b*MM + n*CC;
    float t0 = theta[0], t1 = theta[1];
    float C0 = t0*approx[0] + t1*approx[3];
    float C1 = t0*approx[1] + t1*approx[4];
    float C2 = t0*approx[2] + t1*approx[5];
    float Sr[CC], Si[CC];
    #pragma unroll
    for (int cp = 0; cp < CC; ++cp) {
        int m = mbase + cp;
        float qr[CC], qi[CC];
        #pragma unroll
        for (int c = 0; c < CC; ++c) {
            float2 g = d_g[m*CC + c];
            float2 g2 = d_g2[m*CC + c];
            qr[c] = -C1 * g.x + 2.0f*C2 * g2.x;
            qi[c] = -C1 * g.y + 2.0f*C2 * g2.y;
        }
        float2 sg = d_sg[m];
        qr[cp] += (C0 - C2) * sg.x;
        qi[cp] += (C0 - C2) * sg.y;
        float pr = 0.f, pi = 0.f;
        #pragma unroll
        for (int eo = 0; eo < 4; ++eo) {
            int e = lane + eo*32;
            float yr = 0.f, yi = 0.f;
            #pragma unroll
            for (int c = 0; c < CC; ++c) {
                float ar = d_Ar[c*EE + e], ai = d_Ai[c*EE + e];
                yr += qr[c]*ar - qi[c]*ai;
                yi += qr[c]*ai + qi[c]*ar;
            }
            float hr = siluf(yr), hi = siluf(yi);
            float er = eoWr[e], ei = eoWi[e];
            pr += hr*er - hi*ei;
            pi += hr*ei + hi*er;
        }
        #pragma unroll
        for (int o = 16; o > 0; o >>= 1) {
            pr += __shfl_xor_sync(0xffffffffu, pr, o);
            pi += __shfl_xor_sync(0xffffffffu, pi, o);
        }
        Sr[cp] = pr; Si[cp] = pi;
    }
    const float inv = 0.10206207261596576f;   // 1/sqrt(96)
    float xs[3];
    float sum = 0.f;
    #pragma unroll
    for (int r = 0; r < 3; ++r) {
        int t = lane + r*32;
        float v = Sr[0];
        #pragma unroll
        for (int k = 1; k < CC; ++k) {
            int a = (k*t) % 96;
            v += 2.0f * (Sr[k]*d_tw96c[a] - Si[k]*d_tw96s[a]);
        }
        xs[r] = v * inv;
        sum += xs[r];
    }
    #pragma unroll
    for (int o = 16; o > 0; o >>= 1) sum += __shfl_xor_sync(0xffffffffu, sum, o);
    float mu = sum / 96.0f;
    float ss = 0.f;
    #pragma unroll
    for (int r = 0; r < 3; ++r) { float d = xs[r]-mu; ss += d*d; }
    #pragma unroll
    for (int o = 16; o > 0; o >>= 1) ss += __shfl_xor_sync(0xffffffffu, ss, o);
    float rstd = 1.0f / sqrtf(ss/96.0f + 1e-5f);
    float w = n1w[n], bia = n1b[n];
    #pragma unroll
    for (int r = 0; r < 3; ++r) {
        int t = lane + r*32;
        float h = (xs[r]-mu)*rstd*w + bia;
        d_H[(size_t)row*TT + t] = siluf(h);
    }
}

// ---------------- fused tail: H1 (+inorm+silu) then G then out — warp per row ----------------
// block 256 = 8 rows; 3 smem phases in one 41.6KB union buffer
__global__ void __launch_bounds__(256) k_tail(const float* __restrict__ W1w, const float* __restrict__ W1b,
                                              const float* __restrict__ n2w, const float* __restrict__ n2b,
                                              const float* __restrict__ W2w, const float* __restrict__ W2b,
                                              const float* __restrict__ Wtw, const float* __restrict__ Wtb,
                                              const float* __restrict__ W3w, const float* __restrict__ W3b,
                                              float* __restrict__ out) {
    __shared__ float sbuf[10400];   // 41.6KB union
    // phase 1: W1 [t*65 + h]
    for (int idx = threadIdx.x; idx < HID*TT; idx += 256) {
        int h = idx / TT, t = idx % TT;
        sbuf[t*65 + h] = W1w[idx];
    }
    __syncthreads();
    int row = blockIdx.x * 8 + (threadIdx.x >> 5);
    int lane = threadIdx.x & 31;
    int n = row & 255;
    const float* hr = d_H + (size_t)row*TT;
    float h0 = hr[lane], h1 = hr[lane+32], h2 = hr[lane+64];
    float a0 = W1b[lane], a1 = W1b[lane + 32];
    #pragma unroll
    for (int t = 0; t < TT; ++t) {
        float hv = __shfl_sync(0xffffffffu, (t < 32) ? h0 : ((t < 64) ? h1 : h2), t & 31);
        a0 += hv * sbuf[t*65 + lane];
        a1 += hv * sbuf[t*65 + lane + 32];
    }
    {
        float sum = a0 + a1;
        #pragma unroll
        for (int o = 16; o > 0; o >>= 1) sum += __shfl_xor_sync(0xffffffffu, sum, o);
        float mu = sum / 64.0f;
        float dd0 = a0-mu, dd1 = a1-mu;
        float ss = dd0*dd0 + dd1*dd1;
        #pragma unroll
        for (int o = 16; o > 0; o >>= 1) ss += __shfl_xor_sync(0xffffffffu, ss, o);
        float rstd = 1.0f / sqrtf(ss/64.0f + 1e-5f);
        float w = n2w[n], bb = n2b[n];
        a0 = siluf(dd0*rstd*w + bb);
        a1 = siluf(dd1*rstd*w + bb);
    }
    __syncthreads();
    // phase 2: W2 [k*65+h] @0, Wt [t*65+h] @4160
    for (int idx = threadIdx.x; idx < HID*HID; idx += 256) {
        int h = idx / HID, k = idx % HID;
        sbuf[k*65 + h] = W2w[idx];
    }
    for (int idx = threadIdx.x; idx < HID*TT; idx += 256) {
        int h = idx / TT, t = idx % TT;
        sbuf[4160 + t*65 + h] = Wtw[idx];
    }
    __syncthreads();
    const float* tr = d_trend + (size_t)row*TT;
    float t0 = tr[lane], t1 = tr[lane+32], t2 = tr[lane+64];
    float g0 = W2b[lane] + Wtb[lane];
    float g1 = W2b[lane+32] + Wtb[lane+32];
    #pragma unroll
    for (int k = 0; k < HID; ++k) {
        float hv = __shfl_sync(0xffffffffu, (k < 32) ? a0 : a1, k & 31);
        g0 += hv * sbuf[k*65 + lane];
        g1 += hv * sbuf[k*65 + lane + 32];
    }
    #pragma unroll
    for (int t = 0; t < TT; ++t) {
        float tv = __shfl_sync(0xffffffffu, (t < 32) ? t0 : ((t < 64) ? t1 : t2), t & 31);
        g0 += tv * sbuf[4160 + t*65 + lane];
        g1 += tv * sbuf[4160 + t*65 + lane + 32];
    }
    __syncthreads();
    // phase 3: W3 [h*97 + t]
    for (int idx = threadIdx.x; idx < PRED*HID; idx += 256) {
        int t = idx / HID, h = idx % HID;
        sbuf[h*97 + t] = W3w[idx];
    }
    __syncthreads();
    float o0 = W3b[lane], o1 = W3b[lane+32], o2 = W3b[lane+64];
    #pragma unroll
    for (int h = 0; h < HID; ++h) {
        float gv = __shfl_sync(0xffffffffu, (h < 32) ? g0 : g1, h & 31);
        o0 += gv * sbuf[h*97 + lane];
        o1 += gv * sbuf[h*97 + lane + 32];
        o2 += gv * sbuf[h*97 + lane + 64];
    }
    float* orow = out + (size_t)row*PRED;
    orow[lane]      = o0;
    orow[lane + 32] = o1;
    orow[lane + 64] = o2;
}

// ---------------- launch ----------------
extern "C" void kernel_launch(void* const* d_in, const int* in_sizes, int n_in,
                              void* d_out, int out_size) {
    const float* x     = (const float*)d_in[0];
    const float* approx= (const float*)d_in[1];
    const float* theta = (const float*)d_in[2];
    const float* frWr  = (const float*)d_in[3];
    const float* frWi  = (const float*)d_in[4];
    const float* eoWr  = (const float*)d_in[5];
    const float* eoWi  = (const float*)d_in[6];
    const float* femb  = (const float*)d_in[7];
    const float* n1w   = (const float*)d_in[8];
    const float* n1b   = (const float*)d_in[9];
    const float* n2w   = (const float*)d_in[10];
    const float* n2b   = (const float*)d_in[11];
    const float* W1w   = (const float*)d_in[12];
    const float* W1b   = (const float*)d_in[13];
    const float* W2w   = (const float*)d_in[14];
    const float* W2b   = (const float*)d_in[15];
    const float* Wtw   = (const float*)d_in[16];
    const float* Wtb   = (const float*)d_in[17];
    const float* W3w   = (const float*)d_in[18];
    const float* W3b   = (const float*)d_in[19];
    float* out = (float*)d_out;

    k_init<<<NZB + CC + 1 + NTB, 256>>>(x, femb, frWr, frWi);
    {
        dim3 grid(MM/256, BB, NSL);
        k_knn_part<<<grid, 256>>>();
    }
    k_knn_merge<<<(BM*2 + 255)/256, 256>>>();
    k_gf<<<(BM*2 + 255)/256, 256>>>();
    k_gr<<<(BM*KNN + 255)/256, 256>>>();
    k_g2f<<<(BM*2 + 255)/256, 256>>>();
    k_g2r<<<(BM*KNN + 255)/256, 256>>>();
    k_proj_irfft<<<(BN*32 + 255)/256, 256>>>(approx, theta, eoWr, eoWi, n1w, n1b);
    k_tail<<<BN/8, 256>>>(W1w, W1b, n2w, n2b, W2w, W2b, Wtw, Wtb, W3w, W3b, out);
}

// round 17
// speedup vs baseline: 1.4309x; 1.4309x over previous
#include <cuda_runtime.h>
#include <math.h>

#define BB 16
#define TT 96
#define NN 256
#define CC 9
#define MM (NN*CC)          // 2304
#define EE 128
#define HID 64
#define KNN 8
#define PRED 96
#define BM (BB*MM)          // 36864
#define BN (BB*NN)          // 4096
#define NSL 6               // knn candidate slices (grid 9*16*6=864 = one wave)
#define SLW (MM/NSL)        // 384 candidates per slice
#define CAP 16              // pass-2 collection cap
#define NZB ((BM + 255)/256)      // indeg zero blocks (144)
#define NTB (BN/256)              // trend blocks (16)

// ---------------- device scratch (static, no allocation) ----------------
__device__ float  d_trend[BN*TT];          // (b,n,t)
__device__ float2 d_sg[BM];                // spectral node scalars
__device__ int    d_idx[BM*KNN];
__device__ float  d_indeg[BM];
__device__ float  d_pd[BM*NSL*KNN];        // partial knn distances
__device__ int    d_pi[BM*NSL*KNN];        // partial knn indices
__device__ float2 d_g[BM*CC];              // (r,i) per (node, freq)
__device__ float2 d_g2[BM*CC];
__device__ float  d_H[BN*TT];
__device__ float  d_Ar[CC*EE], d_Ai[CC*EE];
__device__ float  d_tw96c[96], d_tw96s[96];

__device__ __forceinline__ void red_add_f32x2(float2* addr, float a, float b) {
    asm volatile("red.global.add.v2.f32 [%0], {%1, %2};" :: "l"(addr), "f"(a), "f"(b) : "memory");
}

// ---------------- merged: zero indeg + proj-weight precompute + tw96 + trend/DFT ----------------
__global__ void k_init(const float* __restrict__ x,
                       const float* __restrict__ femb,
                       const float* __restrict__ frWr,
                       const float* __restrict__ frWi) {
    int bid = blockIdx.x;
    if (bid < NZB) {
        int i = bid * 256 + threadIdx.x;
        if (i < BM) d_indeg[i] = 0.f;
        return;
    }
    if (bid < NZB + CC + 1) {
        int pb = bid - NZB;                     // 0..CC
        if (threadIdx.x >= 128) return;
        if (pb < CC) {
            int c = pb, e = threadIdx.x;
            float sr = 0.f, si = 0.f;
            const float* fe = femb + c*EE;
            const float* wr = frWr + e*EE;
            const float* wi = frWi + e*EE;
            #pragma unroll 8
            for (int k = 0; k < EE; ++k) {
                float f = fe[k];
                sr += f * wr[k];
                si += f * wi[k];
            }
            d_Ar[c*EE + e] = sr;
            d_Ai[c*EE + e] = si;
        } else {
            int t = threadIdx.x;
            if (t < 96) {
                double a = 2.0 * 3.14159265358979323846 * (double)t / 96.0;
                d_tw96c[t] = (float)cos(a);
                d_tw96s[t] = (float)sin(a);
            }
        }
        return;
    }
    // ---- trend (moving avg) + truncated 16-pt rDFT ----
    int id = (bid - (NZB + CC + 1)) * 256 + threadIdx.x;
    if (id >= BN) return;
    int b = id >> 8, n = id & 255;
    const float* xb = x + (size_t)b*TT*NN + n;
    float twc[16], tws[16];
    #pragma unroll
    for (int t = 0; t < 16; ++t) sincospif(t * 0.125f, &tws[t], &twc[t]);
    float s[16];
    float xprev = xb[0];
    float xc = xb[0];
    for (int t = 0; t < TT; ++t) {
        float xn = (t < TT-1) ? xb[(t+1)*NN] : xc;
        float tr = (xprev + xc + xn) / 3.0f;
        d_trend[(size_t)id*TT + t] = tr;
        if (t < 16) s[t] = xc - tr;
        xprev = xc; xc = xn;
    }
    int base = b*MM + n*CC;
    #pragma unroll
    for (int c = 0; c < CC; ++c) {
        float sr = 0.f, si = 0.f;
        #pragma unroll
        for (int t = 0; t < 16; ++t) {
            int a = (c*t) & 15;
            sr += s[t] * twc[a];
            si -= s[t] * tws[a];
        }
        d_sg[base + c] = make_float2(0.25f * sr, 0.25f * si);
    }
}

// sorted-insert of v into ascending bd[0..7] (distances only): 16 FMNMX, no SELs
#define INS8(v) do { \
    float m0 = fminf(bd[0], (v)); \
    float m1 = fminf(bd[1], (v)); \
    float m2 = fminf(bd[2], (v)); \
    float m3 = fminf(bd[3], (v)); \
    float m4 = fminf(bd[4], (v)); \
    float m5 = fminf(bd[5], (v)); \
    float m6 = fminf(bd[6], (v)); \
    float m7 = fminf(bd[7], (v)); \
    bd[7] = fmaxf(bd[6], m7); \
    bd[6] = fmaxf(bd[5], m6); \
    bd[5] = fmaxf(bd[4], m5); \
    bd[4] = fmaxf(bd[3], m4); \
    bd[3] = fmaxf(bd[2], m3); \
    bd[2] = fmaxf(bd[1], m2); \
    bd[1] = fmaxf(bd[0], m1); \
    bd[0] = m0; \
} while (0)

// composite (d2, j) bubble insert into md/mi8[0..7]
#define INSC(vd_, vi_) do { \
    float vd = (vd_); int vi = (vi_); \
    _Pragma("unroll") \
    for (int k = 0; k < KNN; ++k) { \
        bool lt = (vd < md[k]) || (vd == md[k] && vi < mi8[k]); \
        float od = md[k]; int oi = mi8[k]; \
        md[k]  = lt ? vd : od; \
        mi8[k] = lt ? vi : oi; \
        vd = lt ? od : vd; \
        vi = lt ? oi : vi; \
    } \
} while (0)

// ---------------- KNN partial: two-pass (threshold, then index recovery) ----------------
// d2' = |c|^2 - 2<me, c>  (self-sq dropped: constant per node -> same ordering, merge-safe)
// grid (MM/256, BB, NSL), block 256 — 864 blocks = single wave
__global__ void __launch_bounds__(256) k_knn_part() {
    __shared__ float4 sf[MM];   // (x, y, sq, 0) 36.9KB
    int b = blockIdx.y;
    int z = blockIdx.z;
    for (int m = threadIdx.x; m < MM; m += 256) {
        float2 v = d_sg[b*MM + m];
        sf[m] = make_float4(v.x, v.y, v.x*v.x + v.y*v.y, 0.f);
    }
    __syncthreads();
    int i = blockIdx.x * 256 + threadIdx.x;   // node 0..MM-1
    float4 me = sf[i];
    float n2x = -2.0f * me.x, n2y = -2.0f * me.y;
    const float FINF = __int_as_float(0x7f800000);
    int j0 = z * SLW, j1 = j0 + SLW;
    int e1 = min(j1, i);       // [j0, e1) excludes self
    int s2 = max(j0, i + 1);   // [s2, j1) excludes self
    // ---- pass 1: find the 8 smallest distances (values only) ----
    float bd[KNN];
    #pragma unroll
    for (int k = 0; k < KNN; ++k) bd[k] = FINF;
    #pragma unroll 4
    for (int j = j0; j < e1; ++j) {
        float4 c = sf[j];
        float d2 = fmaf(n2y, c.y, fmaf(n2x, c.x, c.z));
        INS8(d2);
    }
    #pragma unroll 4
    for (int j = s2; j < j1; ++j) {
        float4 c = sf[j];
        float d2 = fmaf(n2y, c.y, fmaf(n2x, c.x, c.z));
        INS8(d2);
    }
    float thr = bd[7];
    // ---- pass 2: collect all j with d2 <= thr (>=8, rarely more than 8) ----
    float cd[CAP]; int cj[CAP];
    int cnt = 0;
    #pragma unroll 4
    for (int j = j0; j < e1; ++j) {
        float4 c = sf[j];
        float d2 = fmaf(n2y, c.y, fmaf(n2x, c.x, c.z));
        if (d2 <= thr) {
            int p = min(cnt, CAP-1);
            cd[p] = d2; cj[p] = j; cnt++;
        }
    }
    #pragma unroll 4
    for (int j = s2; j < j1; ++j) {
        float4 c = sf[j];
        float d2 = fmaf(n2y, c.y, fmaf(n2x, c.x, c.z));
        if (d2 <= thr) {
            int p = min(cnt, CAP-1);
            cd[p] = d2; cj[p] = j; cnt++;
        }
    }
    if (cnt > CAP) cnt = CAP;
    // ---- insertion sort by (d2, j) ascending: exact top_k tie semantics ----
    for (int a = 1; a < cnt; ++a) {
        float vd = cd[a]; int vj = cj[a];
        int p = a;
        while (p > 0 && (cd[p-1] > vd || (cd[p-1] == vd && cj[p-1] > vj))) {
            cd[p] = cd[p-1]; cj[p] = cj[p-1]; --p;
        }
        cd[p] = vd; cj[p] = vj;
    }
    int base = ((b*MM + i)*NSL + z) * KNN;
    #pragma unroll
    for (int k = 0; k < KNN; ++k) { d_pd[base + k] = cd[k]; d_pi[base + k] = cj[k]; }
}

// ---------------- KNN merge: 2 threads/node, float4 loads, snapshot-then-merge ----------------
__global__ void __launch_bounds__(256) k_knn_merge() {
    int gtid = blockIdx.x * 256 + threadIdx.x;
    int m = gtid >> 1;          // node
    int half = gtid & 1;        // 0: slices 0-2, 1: slices 3-5
    if (m >= BM) return;
    int b = m / MM;
    const float FINF = __int_as_float(0x7f800000);
    float md[KNN]; int mi8[KNN];
    #pragma unroll
    for (int k = 0; k < KNN; ++k) { md[k] = FINF; mi8[k] = 0x7fffffff; }
    const float4* pd4 = (const float4*)&d_pd[m*(NSL*KNN) + half*24];
    const int4*  pi4 = (const int4*) &d_pi[m*(NSL*KNN) + half*24];
    #pragma unroll
    for (int v = 0; v < 6; ++v) {
        float4 dv = pd4[v];
        int4  jv = pi4[v];
        INSC(dv.x, jv.x);
        INSC(dv.y, jv.y);
        INSC(dv.z, jv.z);
        INSC(dv.w, jv.w);
    }
    // snapshot partner's PRE-merge list first (avoids register race), then merge
    float pdl[KNN]; int pjl[KNN];
    #pragma unroll
    for (int k = 0; k < KNN; ++k) {
        pdl[k] = __shfl_xor_sync(0xffffffffu, md[k], 1);
        pjl[k] = __shfl_xor_sync(0xffffffffu, mi8[k], 1);
    }
    #pragma unroll
    for (int k = 0; k < KNN; ++k) INSC(pdl[k], pjl[k]);
    if (half == 0) {
        #pragma unroll
        for (int k = 0; k < KNN; ++k) {
            d_idx[m*KNN + k] = mi8[k];
            atomicAdd(&d_indeg[b*MM + mi8[k]], 1.0f);
        }
    }
}

// ---------------- g forward gather: thread-per-node, writes d_g (no zero needed) ----------------
__global__ void k_gf() {
    int i = blockIdx.x * blockDim.x + threadIdx.x;
    if (i >= BM) return;
    int b = i / MM;
    float di = d_indeg[i] + 8.0f + 1e-8f;
    float gr[CC], gi[CC];
    #pragma unroll
    for (int c = 0; c < CC; ++c) { gr[c] = 0.f; gi[c] = 0.f; }
    #pragma unroll
    for (int k = 0; k < KNN; ++k) {
        int j = b*MM + d_idx[i*KNN + k];
        float w = 0.5f * rsqrtf(di * (d_indeg[j] + 8.0f + 1e-8f));
        float2 s = d_sg[j];
        int cj = j % CC;
        float wx = w*s.x, wy = w*s.y;
        #pragma unroll
        for (int c = 0; c < CC; ++c) if (c == cj) { gr[c] += wx; gi[c] += wy; }
    }
    #pragma unroll
    for (int c = 0; c < CC; ++c) d_g[i*CC + c] = make_float2(gr[c], gi[c]);
}

// ---------------- g reverse scatter: 1 red.v2 per edge ----------------
__global__ void k_gr() {
    int e = blockIdx.x * blockDim.x + threadIdx.x;
    if (e >= BM*KNN) return;
    int mi = e >> 3;
    int b = mi / MM;
    int mj = b*MM + d_idx[e];
    float w = 0.5f * rsqrtf((d_indeg[mi]+8.0f+1e-8f) * (d_indeg[mj]+8.0f+1e-8f));
    int ci = mi % CC;
    float2 si = d_sg[mi];
    red_add_f32x2(&d_g[mj*CC + ci], w*si.x, w*si.y);
}

// ---------------- g2 forward gather: thread-per-node, writes d_g2 ----------------
__global__ void k_g2f() {
    int i = blockIdx.x * blockDim.x + threadIdx.x;
    if (i >= BM) return;
    int b = i / MM;
    float di = d_indeg[i] + 8.0f + 1e-8f;
    float ar[CC], ai[CC];
    #pragma unroll
    for (int c = 0; c < CC; ++c) { ar[c] = 0.f; ai[c] = 0.f; }
    #pragma unroll
    for (int k = 0; k < KNN; ++k) {
        int j = b*MM + d_idx[i*KNN + k];
        float w = 0.5f * rsqrtf(di * (d_indeg[j] + 8.0f + 1e-8f));
        #pragma unroll
        for (int c = 0; c < CC; ++c) {
            float2 gj = d_g[j*CC + c];
            ar[c] += w * gj.x;
            ai[c] += w * gj.y;
        }
    }
    #pragma unroll
    for (int c = 0; c < CC; ++c) d_g2[i*CC + c] = make_float2(ar[c], ai[c]);
}

// ---------------- g2 reverse scatter: 9 red.v2 per edge ----------------
__global__ void k_g2r() {
    int e = blockIdx.x * blockDim.x + threadIdx.x;
    if (e >= BM*KNN) return;
    int mi = e >> 3;
    int b = mi / MM;
    int mj = b*MM + d_idx[e];
    float w = 0.5f * rsqrtf((d_indeg[mi]+8.0f+1e-8f) * (d_indeg[mj]+8.0f+1e-8f));
    #pragma unroll
    for (int c = 0; c < CC; ++c) {
        float2 gi = d_g[mi*CC + c];
        red_add_f32x2(&d_g2[mj*CC + c], w*gi.x, w*gi.y);
    }
}

// fast silu: MUFU-based exp + divide (rel err ~1e-6, tol is 1e-3)
__device__ __forceinline__ float siluf(float v) {
    return __fdividef(v, 1.0f + __expf(-v));
}

// ---------------- fused: proj (9 nodes) + irfft(96) + inorm + silu, warp per (b,n) row ----------------
__global__ void __launch_bounds__(256) k_proj_irfft(const float* __restrict__ approx,
                                                    const float* __restrict__ theta,
                                                    const float* __restrict__ eoWr,
                                                    const float* __restrict__ eoWi,
                                                    const float* __restrict__ n1w,
                                                    const float* __restrict__ n1b) {
    int gtid = blockIdx.x * blockDim.x + threadIdx.x;
    int row = gtid >> 5;
    int lane = gtid & 31;
    if (row >= BN) return;
    int b = row >> 8, n = row & 255;
    int mbase = b*MM + n*CC;
    float t0 = theta[0], t1 = theta[1];
    float C0 = t0*approx[0] + t1*approx[3];
    float C1 = t0*approx[1] + t1*approx[4];
    float C2 = t0*approx[2] + t1*approx[5];
    float Sr[CC], Si[CC];
    #pragma unroll
    for (int cp = 0; cp < CC; ++cp) {
        int m = mbase + cp;
        float qr[CC], qi[CC];
        #pragma unroll
        for (int c = 0; c < CC; ++c) {
            float2 g = d_g[m*CC + c];
            float2 g2 = d_g2[m*CC + c];
            qr[c] = -C1 * g.x + 2.0f*C2 * g2.x;
            qi[c] = -C1 * g.y + 2.0f*C2 * g2.y;
        }
        float2 sg = d_sg[m];
        qr[cp] += (C0 - C2) * sg.x;
        qi[cp] += (C0 - C2) * sg.y;
        float pr = 0.f, pi = 0.f;
        #pragma unroll
        for (int eo = 0; eo < 4; ++eo) {
            int e = lane + eo*32;
            float yr = 0.f, yi = 0.f;
            #pragma unroll
            for (int c = 0; c < CC; ++c) {
                float ar = d_Ar[c*EE + e], ai = d_Ai[c*EE + e];
                yr += qr[c]*ar - qi[c]*ai;
                yi += qr[c]*ai + qi[c]*ar;
            }
            float hr = siluf(yr), hi = siluf(yi);
            float er = eoWr[e], ei = eoWi[e];
            pr += hr*er - hi*ei;
            pi += hr*ei + hi*er;
        }
        #pragma unroll
        for (int o = 16; o > 0; o >>= 1) {
            pr += __shfl_xor_sync(0xffffffffu, pr, o);
            pi += __shfl_xor_sync(0xffffffffu, pi, o);
        }
        Sr[cp] = pr; Si[cp] = pi;
    }
    const float inv = 0.10206207261596576f;   // 1/sqrt(96)
    float xs[3];
    float sum = 0.f;
    #pragma unroll
    for (int r = 0; r < 3; ++r) {
        int t = lane + r*32;
        float v = Sr[0];
        #pragma unroll
        for (int k = 1; k < CC; ++k) {
            int a = (k*t) % 96;
            v += 2.0f * (Sr[k]*d_tw96c[a] - Si[k]*d_tw96s[a]);
        }
        xs[r] = v * inv;
        sum += xs[r];
    }
    #pragma unroll
    for (int o = 16; o > 0; o >>= 1) sum += __shfl_xor_sync(0xffffffffu, sum, o);
    float mu = sum / 96.0f;
    float ss = 0.f;
    #pragma unroll
    for (int r = 0; r < 3; ++r) { float d = xs[r]-mu; ss += d*d; }
    #pragma unroll
    for (int o = 16; o > 0; o >>= 1) ss += __shfl_xor_sync(0xffffffffu, ss, o);
    float rstd = 1.0f / sqrtf(ss/96.0f + 1e-5f);
    float w = n1w[n], bia = n1b[n];
    #pragma unroll
    for (int r = 0; r < 3; ++r) {
        int t = lane + r*32;
        float h = (xs[r]-mu)*rstd*w + bia;
        d_H[(size_t)row*TT + t] = siluf(h);
    }
}

// ---------------- fused tail: H1 (+inorm+silu) then G then out — warp per row ----------------
// block 256 = 8 rows; 3 smem phases in one 41.6KB union buffer
__global__ void __launch_bounds__(256) k_tail(const float* __restrict__ W1w, const float* __restrict__ W1b,
                                              const float* __restrict__ n2w, const float* __restrict__ n2b,
                                              const float* __restrict__ W2w, const float* __restrict__ W2b,
                                              const float* __restrict__ Wtw, const float* __restrict__ Wtb,
                                              const float* __restrict__ W3w, const float* __restrict__ W3b,
                                              float* __restrict__ out) {
    __shared__ float sbuf[10400];   // 41.6KB union
    // phase 1: W1 [t*65 + h]
    for (int idx = threadIdx.x; idx < HID*TT; idx += 256) {
        int h = idx / TT, t = idx % TT;
        sbuf[t*65 + h] = W1w[idx];
    }
    __syncthreads();
    int row = blockIdx.x * 8 + (threadIdx.x >> 5);
    int lane = threadIdx.x & 31;
    int n = row & 255;
    const float* hr = d_H + (size_t)row*TT;
    float h0 = hr[lane], h1 = hr[lane+32], h2 = hr[lane+64];
    float a0 = W1b[lane], a1 = W1b[lane + 32];
    #pragma unroll
    for (int t = 0; t < TT; ++t) {
        float hv = __shfl_sync(0xffffffffu, (t < 32) ? h0 : ((t < 64) ? h1 : h2), t & 31);
        a0 += hv * sbuf[t*65 + lane];
        a1 += hv * sbuf[t*65 + lane + 32];
    }
    {
        float sum = a0 + a1;
        #pragma unroll
        for (int o = 16; o > 0; o >>= 1) sum += __shfl_xor_sync(0xffffffffu, sum, o);
        float mu = sum / 64.0f;
        float dd0 = a0-mu, dd1 = a1-mu;
        float ss = dd0*dd0 + dd1*dd1;
        #pragma unroll
        for (int o = 16; o > 0; o >>= 1) ss += __shfl_xor_sync(0xffffffffu, ss, o);
        float rstd = 1.0f / sqrtf(ss/64.0f + 1e-5f);
        float w = n2w[n], bb = n2b[n];
        a0 = siluf(dd0*rstd*w + bb);
        a1 = siluf(dd1*rstd*w + bb);
    }
    __syncthreads();
    // phase 2: W2 [k*65+h] @0, Wt [t*65+h] @4160
    for (int idx = threadIdx.x; idx < HID*HID; idx += 256) {
        int h = idx / HID, k = idx % HID;
        sbuf[k*65 + h] = W2w[idx];
    }
    for (int idx = threadIdx.x; idx < HID*TT; idx += 256) {
        int h = idx / TT, t = idx % TT;
        sbuf[4160 + t*65 + h] = Wtw[idx];
    }
    __syncthreads();
    const float* tr = d_trend + (size_t)row*TT;
    float t0 = tr[lane], t1 = tr[lane+32], t2 = tr[lane+64];
    float g0 = W2b[lane] + Wtb[lane];
    float g1 = W2b[lane+32] + Wtb[lane+32];
    #pragma unroll
    for (int k = 0; k < HID; ++k) {
        float hv = __shfl_sync(0xffffffffu, (k < 32) ? a0 : a1, k & 31);
        g0 += hv * sbuf[k*65 + lane];
        g1 += hv * sbuf[k*65 + lane + 32];
    }
    #pragma unroll
    for (int t = 0; t < TT; ++t) {
        float tv = __shfl_sync(0xffffffffu, (t < 32) ? t0 : ((t < 64) ? t1 : t2), t & 31);
        g0 += tv * sbuf[4160 + t*65 + lane];
        g1 += tv * sbuf[4160 + t*65 + lane + 32];
    }
    __syncthreads();
    // phase 3: W3 [h*97 + t]
    for (int idx = threadIdx.x; idx < PRED*HID; idx += 256) {
        int t = idx / HID, h = idx % HID;
        sbuf[h*97 + t] = W3w[idx];
    }
    __syncthreads();
    float o0 = W3b[lane], o1 = W3b[lane+32], o2 = W3b[lane+64];
    #pragma unroll
    for (int h = 0; h < HID; ++h) {
        float gv = __shfl_sync(0xffffffffu, (h < 32) ? g0 : g1, h & 31);
        o0 += gv * sbuf[h*97 + lane];
        o1 += gv * sbuf[h*97 + lane + 32];
        o2 += gv * sbuf[h*97 + lane + 64];
    }
    float* orow = out + (size_t)row*PRED;
    orow[lane]      = o0;
    orow[lane + 32] = o1;
    orow[lane + 64] = o2;
}

// ---------------- launch ----------------
extern "C" void kernel_launch(void* const* d_in, const int* in_sizes, int n_in,
                              void* d_out, int out_size) {
    const float* x     = (const float*)d_in[0];
    const float* approx= (const float*)d_in[1];
    const float* theta = (const float*)d_in[2];
    const float* frWr  = (const float*)d_in[3];
    const float* frWi  = (const float*)d_in[4];
    const float* eoWr  = (const float*)d_in[5];
    const float* eoWi  = (const float*)d_in[6];
    const float* femb  = (const float*)d_in[7];
    const float* n1w   = (const float*)d_in[8];
    const float* n1b   = (const float*)d_in[9];
    const float* n2w   = (const float*)d_in[10];
    const float* n2b   = (const float*)d_in[11];
    const float* W1w   = (const float*)d_in[12];
    const float* W1b   = (const float*)d_in[13];
    const float* W2w   = (const float*)d_in[14];
    const float* W2b   = (const float*)d_in[15];
    const float* Wtw   = (const float*)d_in[16];
    const float* Wtb   = (const float*)d_in[17];
    const float* W3w   = (const float*)d_in[18];
    const float* W3b   = (const float*)d_in[19];
    float* out = (float*)d_out;

    k_init<<<NZB + CC + 1 + NTB, 256>>>(x, femb, frWr, frWi);
    {
        dim3 grid(MM/256, BB, NSL);
        k_knn_part<<<grid, 256>>>();
    }
    k_knn_merge<<<(BM*2 + 255)/256, 256>>>();
    k_gf<<<(BM + 255)/256, 256>>>();
    k_gr<<<(BM*KNN + 255)/256, 256>>>();
    k_g2f<<<(BM + 255)/256, 256>>>();
    k_g2r<<<(BM*KNN + 255)/256, 256>>>();
    k_proj_irfft<<<(BN*32 + 255)/256, 256>>>(approx, theta, eoWr, eoWi, n1w, n1b);
    k_tail<<<BN/8, 256>>>(W1w, W1b, n2w, n2b, W2w, W2b, Wtw, Wtb, W3w, W3b, out);
}